// round 1
// baseline (speedup 1.0000x reference)
#include <cuda_runtime.h>

// Problem shape
#define B_DIM 4096
#define T_DIM 256
#define D_DIM 64
#define TD (T_DIM * D_DIM)   // stride per batch row in inputs/out

#define PA 65                // padded row stride for expm smem buffers (scalar LDS, conflict-free)
#define PB 68                // padded row stride for traj smem (float4-aligned)

// Precomputed expm(K*t), stored TRANSPOSED: g_matsT[t*4096 + j*64 + i] = mats[t][i][j]
__device__ float g_matsT[T_DIM * D_DIM * D_DIM];

// 64x64 smem matmul: C = A * B. 256 threads, 4x4 microtile per thread.
// Caller must __syncthreads() before (operands ready) and after (before consuming C).
__device__ __forceinline__ void mm64(float* __restrict__ C,
                                     const float* __restrict__ A,
                                     const float* __restrict__ B,
                                     int ty, int tx) {
    float acc[4][4];
#pragma unroll
    for (int r = 0; r < 4; r++)
#pragma unroll
        for (int c = 0; c < 4; c++) acc[r][c] = 0.f;

#pragma unroll 4
    for (int k = 0; k < 64; k++) {
        float a[4], b[4];
#pragma unroll
        for (int r = 0; r < 4; r++) a[r] = A[(ty * 4 + r) * PA + k];
#pragma unroll
        for (int c = 0; c < 4; c++) b[c] = B[k * PA + tx * 4 + c];
#pragma unroll
        for (int r = 0; r < 4; r++)
#pragma unroll
            for (int c = 0; c < 4; c++) acc[r][c] = fmaf(a[r], b[c], acc[r][c]);
    }
#pragma unroll
    for (int r = 0; r < 4; r++)
#pragma unroll
        for (int c = 0; c < 4; c++) C[(ty * 4 + r) * PA + tx * 4 + c] = acc[r][c];
}

// One block per t. expm(K*t) via degree-12 Taylor (Paterson-Stockmeyer) on A = K*t/2,
// then one squaring. 6 matmuls total.
extern "C" __global__ void __launch_bounds__(256)
expm_kernel(const float* __restrict__ Kmat, const float* __restrict__ time) {
    extern __shared__ float sm[];
    float* a = sm;             // A = K*t/2
    float* b = a + 64 * PA;    // A^2
    float* c = b + 64 * PA;    // A^4
    float* d = c + 64 * PA;    // A^3
    float* e = d + 64 * PA;    // scratch (poly combos)
    float* f = e + 64 * PA;    // scratch (products / result)

    const int tid = threadIdx.x;
    const int ty = tid >> 4, tx = tid & 15;
    const int bt = blockIdx.x;
    const float t = time[bt] * 0.5f;   // scaling step s=1

    // a = K * (t/2)
#pragma unroll
    for (int l = 0; l < 16; l++) {
        int idx = tid + l * 256;
        a[(idx >> 6) * PA + (idx & 63)] = Kmat[idx] * t;
    }
    __syncthreads();

    mm64(b, a, a, ty, tx);            // A^2
    __syncthreads();
    mm64(c, b, b, ty, tx);            // A^4
    mm64(d, b, a, ty, tx);            // A^3   (reads a,b; writes d — disjoint from c)
    __syncthreads();

    // e = c8*I + c9*A + c10*A2 + c11*A3 + c12*A4
#pragma unroll
    for (int l = 0; l < 16; l++) {
        int idx = tid + l * 256;
        int i = idx >> 6, j = idx & 63;
        int off = i * PA + j;
        float v = 2.4801587301e-5f * ((i == j) ? 1.f : 0.f)
                + 2.7557319224e-6f * a[off]
                + 2.7557319224e-7f * b[off]
                + 2.5052108385e-8f * d[off]
                + 2.0876756988e-9f * c[off];
        e[off] = v;
    }
    __syncthreads();
    mm64(f, c, e, ty, tx);            // A4 * C2'
    __syncthreads();

    // e = c4*I + c5*A + c6*A2 + c7*A3 + f
#pragma unroll
    for (int l = 0; l < 16; l++) {
        int idx = tid + l * 256;
        int i = idx >> 6, j = idx & 63;
        int off = i * PA + j;
        float v = 4.1666666667e-2f * ((i == j) ? 1.f : 0.f)
                + 8.3333333333e-3f * a[off]
                + 1.3888888889e-3f * b[off]
                + 1.9841269841e-4f * d[off]
                + f[off];
        e[off] = v;
    }
    __syncthreads();
    mm64(f, c, e, ty, tx);            // A4 * (C1 + ...)
    __syncthreads();

    // e = I + A + A2/2 + A3/6 + f   == expm(A), degree 12
#pragma unroll
    for (int l = 0; l < 16; l++) {
        int idx = tid + l * 256;
        int i = idx >> 6, j = idx & 63;
        int off = i * PA + j;
        float v = ((i == j) ? 1.f : 0.f)
                + a[off]
                + 0.5f * b[off]
                + 1.6666666667e-1f * d[off]
                + f[off];
        e[off] = v;
    }
    __syncthreads();
    mm64(f, e, e, ty, tx);            // squaring: expm(K*t) = expm(A)^2
    __syncthreads();

    // Store transposed: g_matsT[bt][j][i] = f[i][j]  (coalesced STG, strided LDS gather)
#pragma unroll
    for (int l = 0; l < 16; l++) {
        int o = tid + l * 256;        // o = j*64 + i
        g_matsT[bt * 4096 + o] = f[(o & 63) * PA + (o >> 6)];
    }
}

// Main GEMM: out[b, t, i] = sum_j mats[t][i][j] * x0[b][j]
// Block: one t (blockIdx.y), 64 batch rows (blockIdx.x). 256 threads, 4x4 microtile (b x i).
extern "C" __global__ void __launch_bounds__(256)
traj_kernel(const float* __restrict__ inputs, float* __restrict__ out) {
    __shared__ float mt[64 * PB];   // mt[j][i] = mats[t][i][j]
    __shared__ float xt[64 * PB];   // xt[j][b_local] = x0[b0+b_local][j]

    const int tid = threadIdx.x;
    const int tx = tid & 15;        // i-tile index
    const int ty = tid >> 4;        // b-tile index
    const int t = blockIdx.y;
    const int b0 = blockIdx.x * 64;

    // Load mats[t] (already transposed) into smem, float4 coalesced
    const float4* msrc = (const float4*)(g_matsT + t * 4096);
#pragma unroll
    for (int v = 0; v < 4; v++) {
        int idx4 = v * 256 + tid;            // float4 index over 1024
        int el = idx4 * 4;
        int j = el >> 6, i = el & 63;
        *(float4*)&mt[j * PB + i] = msrc[idx4];
    }

    // Load x0 tile transposed: 64 rows of inputs[:,0,:]
    {
        int bl = tid >> 2;                   // 0..63
        int seg = tid & 3;                   // 0..3, each covers 16 j's
        const float* gp = inputs + (size_t)(b0 + bl) * TD + seg * 16;
#pragma unroll
        for (int q = 0; q < 4; q++) {
            float4 v = *(const float4*)(gp + q * 4);
            int j = seg * 16 + q * 4;
            xt[(j + 0) * PB + bl] = v.x;
            xt[(j + 1) * PB + bl] = v.y;
            xt[(j + 2) * PB + bl] = v.z;
            xt[(j + 3) * PB + bl] = v.w;
        }
    }
    __syncthreads();

    float acc[4][4];
#pragma unroll
    for (int r = 0; r < 4; r++)
#pragma unroll
        for (int c = 0; c < 4; c++) acc[r][c] = 0.f;

#pragma unroll 8
    for (int j = 0; j < 64; j++) {
        float4 av = *(const float4*)&mt[j * PB + tx * 4];   // mats[t][i0..i0+3][j]
        float4 bv = *(const float4*)&xt[j * PB + ty * 4];   // x0[b0+ty*4 .. +3][j]
        float am[4] = {av.x, av.y, av.z, av.w};
        float bm[4] = {bv.x, bv.y, bv.z, bv.w};
#pragma unroll
        for (int r = 0; r < 4; r++)
#pragma unroll
            for (int c = 0; c < 4; c++)
                acc[r][c] = fmaf(bm[r], am[c], acc[r][c]);
    }

    // Store: i contiguous (float4), fully coalesced across tx
#pragma unroll
    for (int r = 0; r < 4; r++) {
        float4 v = make_float4(acc[r][0], acc[r][1], acc[r][2], acc[r][3]);
        *(float4*)(out + (size_t)(b0 + ty * 4 + r) * TD + t * 64 + tx * 4) = v;
    }
}

extern "C" void kernel_launch(void* const* d_in, const int* in_sizes, int n_in,
                              void* d_out, int out_size) {
    const float* inputs = (const float*)d_in[0];
    const float* time   = (const float*)d_in[1];
    const float* kern   = (const float*)d_in[2];
    float* out = (float*)d_out;

    const int smemA = 6 * 64 * PA * sizeof(float);   // 97.5 KB
    cudaFuncSetAttribute(expm_kernel, cudaFuncAttributeMaxDynamicSharedMemorySize, smemA);

    expm_kernel<<<T_DIM, 256, smemA>>>(kern, time);
    traj_kernel<<<dim3(B_DIM / 64, T_DIM), 256>>>(inputs, out);
}